// round 11
// baseline (speedup 1.0000x reference)
#include <cuda_runtime.h>
#include <cuda_fp16.h>
#include <cstdint>

#define B_   32
#define N_   512
#define K1_  256
#define O_   256
#define EPSF 1e-8f

// ---- GEMM tiling: CTA 128m x 256n, warp tile 64x64 (8 warps, 2x4), KC=32 ---
#define KC      32
#define A_ROW   80                         // 32 fp16 (64B) + 16B pad
#define A_PLANE (128 * A_ROW)              // 10240
#define B_ROW   528                        // 256 fp16 (512B) + 16B pad
#define B_PLANE (KC * B_ROW)               // 16896
#define AUX_SZ  2048
#define STAGE   (A_PLANE + B_PLANE)        // 27136
#define OFF_A   0
#define OFF_B   A_PLANE
#define NSTAGE  4
#define SMEM_TOTAL (AUX_SZ + NSTAGE * STAGE)   // 110592, 1 CTA/SM

// ---- scratch: all operands pre-converted to fp16 in prep -------------------
__device__ __align__(16) float    g_dis[B_ * N_];
__device__ __align__(16) uint32_t g_A16[B_ * N_ * N_ / 2];   // A fp16 [b][i][j]
__device__ __align__(16) uint32_t g_H16[B_ * N_ * K1_ / 2];  // H fp16 [m][k]
__device__ __align__(16) uint32_t g_HsH[B_ * N_ * O_ / 2];   // Hs fp16 [b][j][o]
__device__ __align__(16) uint32_t g_WtH[K1_ * O_ / 2];       // W^T fp16 [k][o]

// ---- helpers ----------------------------------------------------------------
__device__ __forceinline__ void ldsm_x4(uint32_t& r0, uint32_t& r1, uint32_t& r2,
                                        uint32_t& r3, uint32_t addr) {
    asm volatile("ldmatrix.sync.aligned.m8n8.x4.shared.b16 {%0,%1,%2,%3}, [%4];"
                 : "=r"(r0), "=r"(r1), "=r"(r2), "=r"(r3) : "r"(addr));
}
__device__ __forceinline__ void ldsm_x4t(uint32_t& r0, uint32_t& r1, uint32_t& r2,
                                         uint32_t& r3, uint32_t addr) {
    asm volatile("ldmatrix.sync.aligned.m8n8.x4.trans.shared.b16 {%0,%1,%2,%3}, [%4];"
                 : "=r"(r0), "=r"(r1), "=r"(r2), "=r"(r3) : "r"(addr));
}
__device__ __forceinline__ void mma16816(float* c,
                                         uint32_t a0, uint32_t a1, uint32_t a2, uint32_t a3,
                                         uint32_t b0, uint32_t b1) {
    asm volatile("mma.sync.aligned.m16n8k16.row.col.f32.f16.f16.f32 "
                 "{%0,%1,%2,%3}, {%4,%5,%6,%7}, {%8,%9}, {%0,%1,%2,%3};"
                 : "+f"(c[0]), "+f"(c[1]), "+f"(c[2]), "+f"(c[3])
                 : "r"(a0), "r"(a1), "r"(a2), "r"(a3), "r"(b0), "r"(b1));
}
__device__ __forceinline__ uint32_t packh2(float v0, float v1) {
    __half2 h = __floats2half2_rn(v0, v1);
    return *reinterpret_cast<uint32_t*>(&h);
}
__device__ __forceinline__ float2 unpackh2(uint32_t q) {
    __half2 h = *reinterpret_cast<__half2*>(&q);
    return __half22float2(h);
}
__device__ __forceinline__ void cpa16(uint32_t dst, const void* src) {
    asm volatile("cp.async.cg.shared.global [%0], [%1], 16;" :: "r"(dst), "l"(src));
}
#define CP_COMMIT() asm volatile("cp.async.commit_group;" ::: "memory")
#define CP_WAIT(n)  asm volatile("cp.async.wait_group %0;" :: "n"(n) : "memory")

// per-chunk mma: KC=32 (2 k-halves), warp tile 64x64, wm in {0,1}, wn in {0..3}
__device__ __forceinline__ void chunk_mma32(float acc[4][8][4], uint32_t bufb,
                                            int wm, int wn, int lane) {
    const uint32_t arow = (uint32_t)((lane & 7) + ((lane >> 3) & 1) * 8);
#pragma unroll
    for (int kh = 0; kh < 2; kh++) {
        const uint32_t a_base = bufb + OFF_A + (wm * 64 + arow) * A_ROW
                              + kh * 32 + (lane >> 4) * 16;
        uint32_t a[4][4], bb[8][2];
#pragma unroll
        for (int mi = 0; mi < 4; mi++)
            ldsm_x4(a[mi][0], a[mi][1], a[mi][2], a[mi][3], a_base + mi * 16 * A_ROW);
#pragma unroll
        for (int p = 0; p < 4; p++) {
            const uint32_t baddr = bufb + OFF_B + (kh * 16 + (lane & 15)) * B_ROW
                                 + (wn * 64 + p * 16 + (lane >> 4) * 8) * 2;
            ldsm_x4t(bb[2 * p][0], bb[2 * p][1], bb[2 * p + 1][0], bb[2 * p + 1][1], baddr);
        }
#pragma unroll
        for (int mi = 0; mi < 4; mi++)
#pragma unroll
            for (int n = 0; n < 8; n++)
                mma16816(acc[mi][n], a[mi][0], a[mi][1], a[mi][2], a[mi][3],
                         bb[n][0], bb[n][1]);
    }
}

// ---------------------------------------------------------------------------
// prep: [0,512): A -> deg + A16; [512,768): H -> H16; [768,832): W^T fp16.
// ---------------------------------------------------------------------------
__global__ __launch_bounds__(256)
void prep_kernel(const float* __restrict__ A, const float* __restrict__ H,
                 const float* __restrict__ W) {
    __shared__ float tile[32][33];
    const int t = threadIdx.x;
    if (blockIdx.x < 512) {
        int wid = t >> 5, lane = t & 31;
        int row0 = (blockIdx.x * 8 + wid) * 4;
        const float4* a = reinterpret_cast<const float4*>(A + (size_t)row0 * N_);
        uint2* a16 = reinterpret_cast<uint2*>(g_A16);
        float s[4] = {0.f, 0.f, 0.f, 0.f};
#pragma unroll
        for (int c = 0; c < 4; c++)
#pragma unroll
            for (int r = 0; r < 4; r++) {
                float4 v = a[(size_t)r * 128 + lane + c * 32];
                s[r] += (v.x + v.y) + (v.z + v.w);
                a16[(size_t)(row0 + r) * 128 + lane + c * 32] =
                    make_uint2(packh2(v.x, v.y), packh2(v.z, v.w));
            }
#pragma unroll
        for (int o = 16; o > 0; o >>= 1)
#pragma unroll
            for (int r = 0; r < 4; r++) s[r] += __shfl_xor_sync(0xffffffffu, s[r], o);
        if (lane == 0)
#pragma unroll
            for (int r = 0; r < 4; r++) g_dis[row0 + r] = rsqrtf(s[r] + 1.0f + EPSF);
    } else if (blockIdx.x < 768) {
        int hb = blockIdx.x - 512;             // 64 H rows per block
        const float4* h4 = reinterpret_cast<const float4*>(H) + (size_t)hb * 4096;
        uint4* h16 = reinterpret_cast<uint4*>(g_H16) + (size_t)hb * 2048;
#pragma unroll
        for (int it = 0; it < 8; it++) {
            int gidx = t + it * 256;
            float4 f0 = h4[2 * gidx], f1 = h4[2 * gidx + 1];
            h16[gidx] = make_uint4(packh2(f0.x, f0.y), packh2(f0.z, f0.w),
                                   packh2(f1.x, f1.y), packh2(f1.z, f1.w));
        }
    } else {
        int idx = blockIdx.x - 768;            // 64 tiles: 8x8
        int k0 = (idx & 7) * 32, o0 = (idx >> 3) * 32;
        int tx = t & 31, ty = t >> 5;          // (32, 8)
#pragma unroll
        for (int i = 0; i < 32; i += 8)
            tile[ty + i][tx] = W[(size_t)(o0 + ty + i) * K1_ + k0 + tx];
        __syncthreads();
        int txp = t & 15, typ = t >> 4;        // (16, 16)
#pragma unroll
        for (int i = 0; i < 32; i += 16) {
            int k = typ + i;
            g_WtH[((size_t)(k0 + k) * O_ + o0 + txp * 2) >> 1] =
                packh2(tile[txp * 2][k], tile[txp * 2 + 1][k]);
        }
    }
}

// ---------------------------------------------------------------------------
// GEMM1: Hs[m,o] = dis[m]*(sum_k H[m,k] W[o,k] + b[o]). CTA 128x256 (full O).
// grid 128 m-tiles, 1 CTA/SM. K=256 -> 8 chunks of 32.
// ---------------------------------------------------------------------------
__global__ __launch_bounds__(256, 1)
void gemm1_mma(const float* __restrict__ bias) {
    extern __shared__ char smem[];
    const uint32_t sb = (uint32_t)__cvta_generic_to_shared(smem);
    const int t = threadIdx.x, lane = t & 31, wid = t >> 5;
    const int wm = wid >> 2, wn = wid & 3;
    const int bm = blockIdx.x * 128;

    float* bias_s = reinterpret_cast<float*>(smem);          // 256 f
    float* dis_s  = reinterpret_cast<float*>(smem + 1024);   // 128 f
    if (t < 256) bias_s[t] = bias[t];
    if (t < 128) dis_s[t]  = g_dis[bm + t];

    const char* srcA = reinterpret_cast<const char*>(g_H16)
                     + (size_t)(bm + (t >> 1)) * 512 + (t & 1) * 32;
    const char* srcB = reinterpret_cast<const char*>(g_WtH)
                     + (size_t)(t >> 3) * 512 + (t & 7) * 64;
    const uint32_t soa = sb + AUX_SZ + OFF_A + (t >> 1) * A_ROW + (t & 1) * 32;
    const uint32_t sob = sb + AUX_SZ + OFF_B + (t >> 3) * B_ROW + (t & 7) * 64;

    auto issue = [&](int s, uint32_t buf) {
        uint32_t st = buf * STAGE;
        cpa16(soa + st,      srcA + s * 64);
        cpa16(soa + st + 16, srcA + s * 64 + 16);
        const char* bsc = srcB + (size_t)s * 16384;   // 32 rows * 512B
        cpa16(sob + st,      bsc);
        cpa16(sob + st + 16, bsc + 16);
        cpa16(sob + st + 32, bsc + 32);
        cpa16(sob + st + 48, bsc + 48);
    };

    float acc[4][8][4];
#pragma unroll
    for (int i = 0; i < 4; i++)
#pragma unroll
        for (int j = 0; j < 8; j++)
#pragma unroll
            for (int e = 0; e < 4; e++) acc[i][j][e] = 0.f;

    const int S = K1_ / KC;  // 8
#pragma unroll
    for (int p = 0; p < 3; p++) { issue(p, p); CP_COMMIT(); }

    for (int s = 0; s < S; s++) {
        CP_WAIT(2);
        __syncthreads();
        if (s + 3 < S) issue(s + 3, (uint32_t)((s + 3) & 3));
        CP_COMMIT();
        chunk_mma32(acc, sb + AUX_SZ + (uint32_t)(s & 3) * STAGE, wm, wn, lane);
    }

    // epilogue: +bias, *dis, fp16 pairs to g_HsH
    const int g = lane >> 2, i4 = lane & 3;
#pragma unroll
    for (int mi = 0; mi < 4; mi++) {
        int r0 = wm * 64 + mi * 16 + g;
        float d0 = dis_s[r0], d1 = dis_s[r0 + 8];
        size_t base0 = (size_t)(bm + r0) * O_;
        size_t base1 = base0 + 8 * O_;
#pragma unroll
        for (int n = 0; n < 8; n++) {
            int o = wn * 64 + n * 8 + i4 * 2;
            g_HsH[(base0 + o) >> 1] = packh2((acc[mi][n][0] + bias_s[o]) * d0,
                                             (acc[mi][n][1] + bias_s[o + 1]) * d0);
            g_HsH[(base1 + o) >> 1] = packh2((acc[mi][n][2] + bias_s[o]) * d1,
                                             (acc[mi][n][3] + bias_s[o + 1]) * d1);
        }
    }
}

// ---------------------------------------------------------------------------
// GEMM2: out[b,i,o] = relu(mask*dis_i*(sum_j A[i,j] Hs[j,o] + Hs[i,o])).
// CTA 128x256 (full O), grid (4 i-tiles, 32 b). K=512 -> 16 chunks of 32.
// ---------------------------------------------------------------------------
__global__ __launch_bounds__(256, 1)
void gemm2_mma(const float* __restrict__ mask, float* __restrict__ out) {
    extern __shared__ char smem[];
    const uint32_t sb = (uint32_t)__cvta_generic_to_shared(smem);
    const int t = threadIdx.x, lane = t & 31, wid = t >> 5;
    const int wm = wid >> 2, wn = wid & 3;
    const int i0 = blockIdx.x * 128;
    const int b  = blockIdx.y;

    float* mdis_s = reinterpret_cast<float*>(smem);   // 128 f
    if (t < 128) mdis_s[t] = mask[b * N_ + i0 + t] * g_dis[b * N_ + i0 + t];

    const char* srcA = reinterpret_cast<const char*>(g_A16)
                     + ((size_t)b * N_ + i0 + (t >> 1)) * 1024 + (t & 1) * 32;
    const char* srcB = reinterpret_cast<const char*>(g_HsH)
                     + ((size_t)b * N_ + (t >> 3)) * 512 + (t & 7) * 64;
    const uint32_t soa = sb + AUX_SZ + OFF_A + (t >> 1) * A_ROW + (t & 1) * 32;
    const uint32_t sob = sb + AUX_SZ + OFF_B + (t >> 3) * B_ROW + (t & 7) * 64;

    auto issue = [&](int s, uint32_t buf) {
        uint32_t st = buf * STAGE;
        cpa16(soa + st,      srcA + s * 64);
        cpa16(soa + st + 16, srcA + s * 64 + 16);
        const char* bsc = srcB + (size_t)s * 16384;
        cpa16(sob + st,      bsc);
        cpa16(sob + st + 16, bsc + 16);
        cpa16(sob + st + 32, bsc + 32);
        cpa16(sob + st + 48, bsc + 48);
    };

    float acc[4][8][4];
#pragma unroll
    for (int i = 0; i < 4; i++)
#pragma unroll
        for (int j = 0; j < 8; j++)
#pragma unroll
            for (int e = 0; e < 4; e++) acc[i][j][e] = 0.f;

    const int S = N_ / KC;  // 16
#pragma unroll
    for (int p = 0; p < 3; p++) { issue(p, p); CP_COMMIT(); }

    for (int s = 0; s < S; s++) {
        CP_WAIT(2);
        __syncthreads();
        if (s + 3 < S) issue(s + 3, (uint32_t)((s + 3) & 3));
        CP_COMMIT();
        chunk_mma32(acc, sb + AUX_SZ + (uint32_t)(s & 3) * STAGE, wm, wn, lane);
    }

    // epilogue: + self-loop Hs[i,o] (fp16), * mask*dis_i, relu
    const int g = lane >> 2, i4 = lane & 3;
#pragma unroll
    for (int mi = 0; mi < 4; mi++) {
        int r0 = wm * 64 + mi * 16 + g;
        float md0 = mdis_s[r0], md1 = mdis_s[r0 + 8];
        size_t row0 = ((size_t)b * N_ + i0 + r0) * O_;
        size_t row1 = row0 + 8 * O_;
#pragma unroll
        for (int n = 0; n < 8; n++) {
            int o = wn * 64 + n * 8 + i4 * 2;
            float2 s0 = unpackh2(g_HsH[(row0 + o) >> 1]);
            float2 s1 = unpackh2(g_HsH[(row1 + o) >> 1]);
            out[row0 + o]     = fmaxf(0.f, md0 * (acc[mi][n][0] + s0.x));
            out[row0 + o + 1] = fmaxf(0.f, md0 * (acc[mi][n][1] + s0.y));
            out[row1 + o]     = fmaxf(0.f, md1 * (acc[mi][n][2] + s1.x));
            out[row1 + o + 1] = fmaxf(0.f, md1 * (acc[mi][n][3] + s1.y));
        }
    }
}

// ---------------------------------------------------------------------------
extern "C" void kernel_launch(void* const* d_in, const int* in_sizes, int n_in,
                              void* d_out, int out_size) {
    const float* H    = (const float*)d_in[0];
    const float* A    = (const float*)d_in[1];
    const float* mask = (const float*)d_in[2];
    const float* W    = (const float*)d_in[3];
    const float* bias = (const float*)d_in[4];
    float* out = (float*)d_out;

    cudaFuncSetAttribute(gemm1_mma, cudaFuncAttributeMaxDynamicSharedMemorySize, SMEM_TOTAL);
    cudaFuncSetAttribute(gemm2_mma, cudaFuncAttributeMaxDynamicSharedMemorySize, SMEM_TOTAL);

    prep_kernel<<<832, 256>>>(A, H, W);
    gemm1_mma<<<128, 256, SMEM_TOTAL>>>(bias);
    gemm2_mma<<<dim3(4, B_), 256, SMEM_TOTAL>>>(mask, out);
}

// round 12
// speedup vs baseline: 1.1620x; 1.1620x over previous
#include <cuda_runtime.h>
#include <cuda_fp16.h>
#include <cstdint>

#define B_   32
#define N_   512
#define K1_  256
#define O_   256
#define EPSF 1e-8f

// ---- GEMM tiling: CTA 128m x 128n, warp tile 32x32 (16 warps, 4x4), KC=32 --
#define KC      32
#define A_ROW   80                         // 32 fp16 (64B) + 16B pad
#define A_PLANE (128 * A_ROW)              // 10240
#define B_ROW   272                        // 128 fp16 (256B) + 16B pad
#define B_PLANE (KC * B_ROW)               // 8704
#define AUX_SZ  2048
#define STAGE   (A_PLANE + B_PLANE)        // 18944
#define OFF_A   0
#define OFF_B   A_PLANE
#define NSTAGE  4
#define SMEM_TOTAL (AUX_SZ + NSTAGE * STAGE)   // 77824 -> 2 CTAs/SM (155KB)

// ---- scratch: all operands pre-converted to fp16 in prep -------------------
__device__ __align__(16) float    g_dis[B_ * N_];
__device__ __align__(16) uint32_t g_A16[B_ * N_ * N_ / 2];   // A fp16 [b][i][j]
__device__ __align__(16) uint32_t g_H16[B_ * N_ * K1_ / 2];  // H fp16 [m][k]
__device__ __align__(16) uint32_t g_HsH[B_ * N_ * O_ / 2];   // Hs fp16 [b][j][o]
__device__ __align__(16) uint32_t g_WtH[K1_ * O_ / 2];       // W^T fp16 [k][o]

// ---- helpers ----------------------------------------------------------------
__device__ __forceinline__ void ldsm_x4(uint32_t& r0, uint32_t& r1, uint32_t& r2,
                                        uint32_t& r3, uint32_t addr) {
    asm volatile("ldmatrix.sync.aligned.m8n8.x4.shared.b16 {%0,%1,%2,%3}, [%4];"
                 : "=r"(r0), "=r"(r1), "=r"(r2), "=r"(r3) : "r"(addr));
}
__device__ __forceinline__ void ldsm_x4t(uint32_t& r0, uint32_t& r1, uint32_t& r2,
                                         uint32_t& r3, uint32_t addr) {
    asm volatile("ldmatrix.sync.aligned.m8n8.x4.trans.shared.b16 {%0,%1,%2,%3}, [%4];"
                 : "=r"(r0), "=r"(r1), "=r"(r2), "=r"(r3) : "r"(addr));
}
__device__ __forceinline__ void mma16816(float* c,
                                         uint32_t a0, uint32_t a1, uint32_t a2, uint32_t a3,
                                         uint32_t b0, uint32_t b1) {
    asm volatile("mma.sync.aligned.m16n8k16.row.col.f32.f16.f16.f32 "
                 "{%0,%1,%2,%3}, {%4,%5,%6,%7}, {%8,%9}, {%0,%1,%2,%3};"
                 : "+f"(c[0]), "+f"(c[1]), "+f"(c[2]), "+f"(c[3])
                 : "r"(a0), "r"(a1), "r"(a2), "r"(a3), "r"(b0), "r"(b1));
}
__device__ __forceinline__ uint32_t packh2(float v0, float v1) {
    __half2 h = __floats2half2_rn(v0, v1);
    return *reinterpret_cast<uint32_t*>(&h);
}
__device__ __forceinline__ float2 unpackh2(uint32_t q) {
    __half2 h = *reinterpret_cast<__half2*>(&q);
    return __half22float2(h);
}
__device__ __forceinline__ void cpa16(uint32_t dst, const void* src) {
    asm volatile("cp.async.cg.shared.global [%0], [%1], 16;" :: "r"(dst), "l"(src));
}
#define CP_COMMIT() asm volatile("cp.async.commit_group;" ::: "memory")
#define CP_WAIT(n)  asm volatile("cp.async.wait_group %0;" :: "n"(n) : "memory")

// per-chunk mma: KC=32 (2 k-halves), warp tile 32x32, wm/wn in {0..3}
__device__ __forceinline__ void chunk_mma32(float acc[2][4][4], uint32_t bufb,
                                            int wm, int wn, int lane) {
    const uint32_t arow = (uint32_t)((lane & 7) + ((lane >> 3) & 1) * 8);
#pragma unroll
    for (int kh = 0; kh < 2; kh++) {
        const uint32_t a_base = bufb + OFF_A + (wm * 32 + arow) * A_ROW
                              + kh * 32 + (lane >> 4) * 16;
        uint32_t a[2][4], bb[4][2];
#pragma unroll
        for (int mi = 0; mi < 2; mi++)
            ldsm_x4(a[mi][0], a[mi][1], a[mi][2], a[mi][3], a_base + mi * 16 * A_ROW);
#pragma unroll
        for (int p = 0; p < 2; p++) {
            const uint32_t baddr = bufb + OFF_B + (kh * 16 + (lane & 15)) * B_ROW
                                 + (wn * 32 + p * 16 + (lane >> 4) * 8) * 2;
            ldsm_x4t(bb[2 * p][0], bb[2 * p][1], bb[2 * p + 1][0], bb[2 * p + 1][1], baddr);
        }
#pragma unroll
        for (int mi = 0; mi < 2; mi++)
#pragma unroll
            for (int n = 0; n < 4; n++)
                mma16816(acc[mi][n], a[mi][0], a[mi][1], a[mi][2], a[mi][3],
                         bb[n][0], bb[n][1]);
    }
}

// ---------------------------------------------------------------------------
// prep: [0,512): A -> deg + A16; [512,768): H -> H16; [768,832): W^T fp16.
// ---------------------------------------------------------------------------
__global__ __launch_bounds__(256)
void prep_kernel(const float* __restrict__ A, const float* __restrict__ H,
                 const float* __restrict__ W) {
    __shared__ float tile[32][33];
    const int t = threadIdx.x;
    if (blockIdx.x < 512) {
        int wid = t >> 5, lane = t & 31;
        int row0 = (blockIdx.x * 8 + wid) * 4;
        const float4* a = reinterpret_cast<const float4*>(A + (size_t)row0 * N_);
        uint2* a16 = reinterpret_cast<uint2*>(g_A16);
        float s[4] = {0.f, 0.f, 0.f, 0.f};
#pragma unroll
        for (int c = 0; c < 4; c++)
#pragma unroll
            for (int r = 0; r < 4; r++) {
                float4 v = a[(size_t)r * 128 + lane + c * 32];
                s[r] += (v.x + v.y) + (v.z + v.w);
                a16[(size_t)(row0 + r) * 128 + lane + c * 32] =
                    make_uint2(packh2(v.x, v.y), packh2(v.z, v.w));
            }
#pragma unroll
        for (int o = 16; o > 0; o >>= 1)
#pragma unroll
            for (int r = 0; r < 4; r++) s[r] += __shfl_xor_sync(0xffffffffu, s[r], o);
        if (lane == 0)
#pragma unroll
            for (int r = 0; r < 4; r++) g_dis[row0 + r] = rsqrtf(s[r] + 1.0f + EPSF);
    } else if (blockIdx.x < 768) {
        int hb = blockIdx.x - 512;             // 64 H rows per block
        const float4* h4 = reinterpret_cast<const float4*>(H) + (size_t)hb * 4096;
        uint4* h16 = reinterpret_cast<uint4*>(g_H16) + (size_t)hb * 2048;
#pragma unroll
        for (int it = 0; it < 8; it++) {
            int gidx = t + it * 256;
            float4 f0 = h4[2 * gidx], f1 = h4[2 * gidx + 1];
            h16[gidx] = make_uint4(packh2(f0.x, f0.y), packh2(f0.z, f0.w),
                                   packh2(f1.x, f1.y), packh2(f1.z, f1.w));
        }
    } else {
        int idx = blockIdx.x - 768;            // 64 tiles: 8x8
        int k0 = (idx & 7) * 32, o0 = (idx >> 3) * 32;
        int tx = t & 31, ty = t >> 5;          // (32, 8)
#pragma unroll
        for (int i = 0; i < 32; i += 8)
            tile[ty + i][tx] = W[(size_t)(o0 + ty + i) * K1_ + k0 + tx];
        __syncthreads();
        int txp = t & 15, typ = t >> 4;        // (16, 16)
#pragma unroll
        for (int i = 0; i < 32; i += 16) {
            int k = typ + i;
            g_WtH[((size_t)(k0 + k) * O_ + o0 + txp * 2) >> 1] =
                packh2(tile[txp * 2][k], tile[txp * 2 + 1][k]);
        }
    }
}

// ---------------------------------------------------------------------------
// GEMM1: Hs[m,o] = dis[m]*(sum_k H[m,k] W[o,k] + b[o]). CTA 128x128, 512 thr.
// grid (128 m-tiles, 2 o-tiles), 2 CTAs/SM. K=256 -> 8 chunks of 32.
// ---------------------------------------------------------------------------
__global__ __launch_bounds__(512, 2)
void gemm1_mma(const float* __restrict__ bias) {
    extern __shared__ char smem[];
    const uint32_t sb = (uint32_t)__cvta_generic_to_shared(smem);
    const int t = threadIdx.x, lane = t & 31, wid = t >> 5;
    const int wm = wid >> 2, wn = wid & 3;
    const int bm = blockIdx.x * 128;
    const int bn = blockIdx.y * 128;

    float* bias_s = reinterpret_cast<float*>(smem);          // 128 f
    float* dis_s  = reinterpret_cast<float*>(smem + 1024);   // 128 f
    if (t < 128) { bias_s[t] = bias[bn + t]; dis_s[t] = g_dis[bm + t]; }

    // cp.async: A 4 thr/row (64B), B 16 thr/row (256B)
    const char* srcA = reinterpret_cast<const char*>(g_H16)
                     + (size_t)(bm + (t >> 2)) * 512 + (t & 3) * 16;
    const char* srcB = reinterpret_cast<const char*>(g_WtH)
                     + (size_t)(t >> 4) * 512 + (size_t)bn * 2 + (t & 15) * 16;
    const uint32_t soa = sb + AUX_SZ + OFF_A + (t >> 2) * A_ROW + (t & 3) * 16;
    const uint32_t sob = sb + AUX_SZ + OFF_B + (t >> 4) * B_ROW + (t & 15) * 16;

    auto issue = [&](int s, uint32_t buf) {
        uint32_t st = buf * STAGE;
        cpa16(soa + st, srcA + s * 64);
        cpa16(sob + st, srcB + (size_t)s * 16384);
    };

    float acc[2][4][4];
#pragma unroll
    for (int i = 0; i < 2; i++)
#pragma unroll
        for (int j = 0; j < 4; j++)
#pragma unroll
            for (int e = 0; e < 4; e++) acc[i][j][e] = 0.f;

    const int S = K1_ / KC;  // 8
#pragma unroll
    for (int p = 0; p < 3; p++) { issue(p, p); CP_COMMIT(); }

    for (int s = 0; s < S; s++) {
        CP_WAIT(2);
        __syncthreads();
        if (s + 3 < S) issue(s + 3, (uint32_t)((s + 3) & 3));
        CP_COMMIT();
        chunk_mma32(acc, sb + AUX_SZ + (uint32_t)(s & 3) * STAGE, wm, wn, lane);
    }

    // epilogue: +bias, *dis, fp16 pairs to g_HsH
    const int g = lane >> 2, i4 = lane & 3;
#pragma unroll
    for (int mi = 0; mi < 2; mi++) {
        int r0 = wm * 32 + mi * 16 + g;
        float d0 = dis_s[r0], d1 = dis_s[r0 + 8];
        size_t base0 = (size_t)(bm + r0) * O_ + bn;
        size_t base1 = base0 + 8 * O_;
#pragma unroll
        for (int n = 0; n < 4; n++) {
            int o = wn * 32 + n * 8 + i4 * 2;
            g_HsH[(base0 + o) >> 1] = packh2((acc[mi][n][0] + bias_s[o]) * d0,
                                             (acc[mi][n][1] + bias_s[o + 1]) * d0);
            g_HsH[(base1 + o) >> 1] = packh2((acc[mi][n][2] + bias_s[o]) * d1,
                                             (acc[mi][n][3] + bias_s[o + 1]) * d1);
        }
    }
}

// ---------------------------------------------------------------------------
// GEMM2: out[b,i,o] = relu(mask*dis_i*(sum_j A[i,j] Hs[j,o] + Hs[i,o])).
// CTA 128x128, 512 thr, grid (4, 2, 32). K=512 -> 16 chunks of 32.
// ---------------------------------------------------------------------------
__global__ __launch_bounds__(512, 2)
void gemm2_mma(const float* __restrict__ mask, float* __restrict__ out) {
    extern __shared__ char smem[];
    const uint32_t sb = (uint32_t)__cvta_generic_to_shared(smem);
    const int t = threadIdx.x, lane = t & 31, wid = t >> 5;
    const int wm = wid >> 2, wn = wid & 3;
    const int i0 = blockIdx.x * 128;
    const int bn = blockIdx.y * 128;
    const int b  = blockIdx.z;

    float* mdis_s = reinterpret_cast<float*>(smem);   // 128 f
    if (t < 128) mdis_s[t] = mask[b * N_ + i0 + t] * g_dis[b * N_ + i0 + t];

    const char* srcA = reinterpret_cast<const char*>(g_A16)
                     + ((size_t)b * N_ + i0 + (t >> 2)) * 1024 + (t & 3) * 16;
    const char* srcB = reinterpret_cast<const char*>(g_HsH)
                     + ((size_t)b * N_ + (t >> 4)) * 512 + (size_t)bn * 2 + (t & 15) * 16;
    const uint32_t soa = sb + AUX_SZ + OFF_A + (t >> 2) * A_ROW + (t & 3) * 16;
    const uint32_t sob = sb + AUX_SZ + OFF_B + (t >> 4) * B_ROW + (t & 15) * 16;

    auto issue = [&](int s, uint32_t buf) {
        uint32_t st = buf * STAGE;
        cpa16(soa + st, srcA + s * 64);
        cpa16(sob + st, srcB + (size_t)s * 16384);
    };

    float acc[2][4][4];
#pragma unroll
    for (int i = 0; i < 2; i++)
#pragma unroll
        for (int j = 0; j < 4; j++)
#pragma unroll
            for (int e = 0; e < 4; e++) acc[i][j][e] = 0.f;

    const int S = N_ / KC;  // 16
#pragma unroll
    for (int p = 0; p < 3; p++) { issue(p, p); CP_COMMIT(); }

    for (int s = 0; s < S; s++) {
        CP_WAIT(2);
        __syncthreads();
        if (s + 3 < S) issue(s + 3, (uint32_t)((s + 3) & 3));
        CP_COMMIT();
        chunk_mma32(acc, sb + AUX_SZ + (uint32_t)(s & 3) * STAGE, wm, wn, lane);
    }

    // epilogue: + self-loop Hs[i,o] (fp16), * mask*dis_i, relu
    const int g = lane >> 2, i4 = lane & 3;
#pragma unroll
    for (int mi = 0; mi < 2; mi++) {
        int r0 = wm * 32 + mi * 16 + g;
        float md0 = mdis_s[r0], md1 = mdis_s[r0 + 8];
        size_t row0 = ((size_t)b * N_ + i0 + r0) * O_ + bn;
        size_t row1 = row0 + 8 * O_;
#pragma unroll
        for (int n = 0; n < 4; n++) {
            int o = wn * 32 + n * 8 + i4 * 2;
            float2 s0 = unpackh2(g_HsH[(row0 + o) >> 1]);
            float2 s1 = unpackh2(g_HsH[(row1 + o) >> 1]);
            out[row0 + o]     = fmaxf(0.f, md0 * (acc[mi][n][0] + s0.x));
            out[row0 + o + 1] = fmaxf(0.f, md0 * (acc[mi][n][1] + s0.y));
            out[row1 + o]     = fmaxf(0.f, md1 * (acc[mi][n][2] + s1.x));
            out[row1 + o + 1] = fmaxf(0.f, md1 * (acc[mi][n][3] + s1.y));
        }
    }
}

// ---------------------------------------------------------------------------
extern "C" void kernel_launch(void* const* d_in, const int* in_sizes, int n_in,
                              void* d_out, int out_size) {
    const float* H    = (const float*)d_in[0];
    const float* A    = (const float*)d_in[1];
    const float* mask = (const float*)d_in[2];
    const float* W    = (const float*)d_in[3];
    const float* bias = (const float*)d_in[4];
    float* out = (float*)d_out;

    cudaFuncSetAttribute(gemm1_mma, cudaFuncAttributeMaxDynamicSharedMemorySize, SMEM_TOTAL);
    cudaFuncSetAttribute(gemm2_mma, cudaFuncAttributeMaxDynamicSharedMemorySize, SMEM_TOTAL);

    prep_kernel<<<832, 256>>>(A, H, W);
    gemm1_mma<<<dim3(128, 2), 512, SMEM_TOTAL>>>(bias);
    gemm2_mma<<<dim3(4, 2, B_), 512, SMEM_TOTAL>>>(mask, out);
}